// round 17
// baseline (speedup 1.0000x reference)
#include <cuda_runtime.h>
#include <cuda_fp16.h>
#include <cstdint>
#include <math.h>

#define BB 2
#define SS 2048
#define DD 768
#define FF 3072
#define HH 12
#define NROW (BB*SS)   // 4096

// ---------------------------------------------------------------- scratch
__device__ __half g_t16[NROW*DD];                 // LN1 then LN2 output
__device__ __half g_qb[NROW*DD], g_kb[NROW*DD], g_vb[NROW*DD];
__device__ float  g_x2[NROW*DD];
__device__ __half g_chi[NROW*DD];
__device__ __half g_h1[NROW*FF];
__device__ __half g_wqh[DD*DD];
__device__ __half g_wkh[DD*DD];
__device__ __half g_wvh[DD*DD];
__device__ __half g_woh[DD*DD];
__device__ __half g_w1h[FF*DD];   // [F,D] = w1^T
__device__ __half g_w2h[DD*FF];   // [D,F] = w2^T

// ---------------------------------------------------------------- helpers
__device__ __forceinline__ uint32_t smem_to_u32(const void* p) {
    uint32_t a;
    asm("{ .reg .u64 t; cvta.to.shared.u64 t, %1; cvt.u32.u64 %0, t; }" : "=r"(a) : "l"(p));
    return a;
}
__device__ __forceinline__ void ldsm_x4(uint32_t (&r)[4], uint32_t addr) {
    asm volatile("ldmatrix.sync.aligned.m8n8.x4.shared.b16 {%0,%1,%2,%3}, [%4];"
                 : "=r"(r[0]), "=r"(r[1]), "=r"(r[2]), "=r"(r[3]) : "r"(addr));
}
__device__ __forceinline__ void ldsm_x4_t(uint32_t (&r)[4], uint32_t addr) {
    asm volatile("ldmatrix.sync.aligned.m8n8.x4.trans.shared.b16 {%0,%1,%2,%3}, [%4];"
                 : "=r"(r[0]), "=r"(r[1]), "=r"(r[2]), "=r"(r[3]) : "r"(addr));
}
// fp16 in, fp32 accum
__device__ __forceinline__ void mma_f32a(float (&c)[4], const uint32_t (&a)[4], const uint32_t (&b)[2]) {
    asm volatile("mma.sync.aligned.m16n8k16.row.col.f32.f16.f16.f32 "
                 "{%0,%1,%2,%3}, {%4,%5,%6,%7}, {%8,%9}, {%0,%1,%2,%3};"
                 : "+f"(c[0]), "+f"(c[1]), "+f"(c[2]), "+f"(c[3])
                 : "r"(a[0]), "r"(a[1]), "r"(a[2]), "r"(a[3]), "r"(b[0]), "r"(b[1]));
}
// fp16 in, fp16 accum (candidate 2x rate)
__device__ __forceinline__ void mma_f16a(uint32_t (&c)[2], const uint32_t (&a)[4], const uint32_t (&b)[2]) {
    asm volatile("mma.sync.aligned.m16n8k16.row.col.f16.f16.f16.f16 "
                 "{%0,%1}, {%2,%3,%4,%5}, {%6,%7}, {%0,%1};"
                 : "+r"(c[0]), "+r"(c[1])
                 : "r"(a[0]), "r"(a[1]), "r"(a[2]), "r"(a[3]), "r"(b[0]), "r"(b[1]));
}
__device__ __forceinline__ void cp16(uint32_t dst, const void* src) {
    asm volatile("cp.async.cg.shared.global [%0], [%1], 16;" :: "r"(dst), "l"(src));
}
#define CP_COMMIT() asm volatile("cp.async.commit_group;" ::: "memory")
#define CP_WAIT1()  asm volatile("cp.async.wait_group 1;" ::: "memory")
#define CP_WAIT0()  asm volatile("cp.async.wait_group 0;" ::: "memory")

__device__ __forceinline__ void red_add2(float* addr, float vx, float vy) {
    asm volatile("red.global.add.v2.f32 [%0], {%1, %2};"
                 :: "l"(addr), "f"(vx), "f"(vy) : "memory");
}
__device__ __forceinline__ uint32_t pack_h2(float x, float y) {
    __half2 h = __floats2half2_rn(x, y);
    return *(uint32_t*)&h;
}

// ---------------------------------------------------------------- LayerNorm -> fp16
// zbuf (optional): initialized to x + zbias (residual/bias pre-seed for split-K reds)
__global__ void ln_kernel(const float* __restrict__ x,
                          __half* __restrict__ hi,
                          const float* __restrict__ alpha_p, const float* __restrict__ bias_p,
                          float* __restrict__ zbuf, const float* __restrict__ zbias)
{
    const int row = blockIdx.x;
    const float* xr = x + (size_t)row * DD;
    const int tid = threadIdx.x, lane = tid & 31, wid = tid >> 5;
    __shared__ float red[8], red2[8];
    __shared__ float s_mean, s_scale;

    float v0 = xr[tid], v1 = xr[tid + 256], v2 = xr[tid + 512];

    if (zbuf) {
        float* zr = zbuf + (size_t)row * DD;
        zr[tid]       = v0 + (zbias ? zbias[tid]       : 0.f);
        zr[tid + 256] = v1 + (zbias ? zbias[tid + 256] : 0.f);
        zr[tid + 512] = v2 + (zbias ? zbias[tid + 512] : 0.f);
    }

    float s  = v0 + v1 + v2;
    float s2 = v0 * v0 + v1 * v1 + v2 * v2;
    #pragma unroll
    for (int o = 16; o; o >>= 1) {
        s  += __shfl_xor_sync(0xffffffffu, s, o);
        s2 += __shfl_xor_sync(0xffffffffu, s2, o);
    }
    if (lane == 0) { red[wid] = s; red2[wid] = s2; }
    __syncthreads();
    if (tid == 0) {
        float t = 0.f, t2 = 0.f;
        #pragma unroll
        for (int i = 0; i < 8; i++) { t += red[i]; t2 += red2[i]; }
        const float mean = t / (float)DD;
        const float var = (t2 - (float)DD * mean * mean) / (float)(DD - 1);
        s_mean = mean;
        s_scale = alpha_p[0] / (sqrtf(fmaxf(var, 0.f)) + 1e-6f);
    }
    __syncthreads();
    const float mean = s_mean, scale = s_scale, bias = bias_p[0];

    hi[(size_t)row * DD + tid]       = __float2half((v0 - mean) * scale + bias);
    hi[(size_t)row * DD + tid + 256] = __float2half((v1 - mean) * scale + bias);
    hi[(size_t)row * DD + tid + 512] = __float2half((v2 - mean) * scale + bias);
}

// ---------------------------------------------------------------- merged prologue: weight transpose (64x64, all fp16) + LN1
struct WSArgs {
    const float* W[6];
    __half* Hi[6];
    int Kd[6], Nd[6];
    int start[7];   // start[6] = total ws blocks (64x64 tiles)
};

__global__ void prolog_kernel(WSArgs a,
                              const float* __restrict__ x,
                              __half* __restrict__ thi,
                              const float* __restrict__ alpha_p, const float* __restrict__ bias_p,
                              float* __restrict__ zbuf)
{
    __shared__ float ts[64][65];
    __shared__ float red[8], red2[8];
    __shared__ float s_mean, s_scale;

    const int tid = threadIdx.x;
    int bidx = blockIdx.x;

    if (bidx < a.start[6]) {
        int e = 0;
        while (bidx >= a.start[e + 1]) e++;
        const int rel = bidx - a.start[e];
        const int Kd = a.Kd[e], Nd = a.Nd[e];
        const int nx = Nd / 64;
        const int n0 = (rel % nx) * 64, k0 = (rel / nx) * 64;
        const float* W = a.W[e];
        __half* Hi = a.Hi[e];

        const int r = tid >> 2, c4 = tid & 3;
        const float* wr = W + (size_t)(k0 + r) * Nd + n0;
        #pragma unroll
        for (int j = 0; j < 4; j++) {
            const int col = (j * 4 + c4) * 4;
            float4 v = *(const float4*)(wr + col);
            ts[r][col + 0] = v.x;
            ts[r][col + 1] = v.y;
            ts[r][col + 2] = v.z;
            ts[r][col + 3] = v.w;
        }
        __syncthreads();

        const int nn = tid >> 2, kq = tid & 3;
        const size_t rowo = (size_t)(n0 + nn) * Kd + k0 + kq * 16;
        #pragma unroll
        for (int hh = 0; hh < 2; hh++) {
            float f[8];
            #pragma unroll
            for (int i = 0; i < 8; i++) f[i] = ts[kq * 16 + hh * 8 + i][nn];
            uint4 w;
            w.x = pack_h2(f[0], f[1]); w.y = pack_h2(f[2], f[3]);
            w.z = pack_h2(f[4], f[5]); w.w = pack_h2(f[6], f[7]);
            *(uint4*)(Hi + rowo + hh * 8) = w;
        }
        return;
    }

    // ---- LN1 branch; seed x2 row with x
    const int row = bidx - a.start[6];
    const float* xr = x + (size_t)row * DD;
    const int lane = tid & 31, wid = tid >> 5;

    float v0 = xr[tid], v1 = xr[tid + 256], v2 = xr[tid + 512];
    {
        float* zr = zbuf + (size_t)row * DD;
        zr[tid]       = v0;
        zr[tid + 256] = v1;
        zr[tid + 512] = v2;
    }

    float s  = v0 + v1 + v2;
    float s2 = v0 * v0 + v1 * v1 + v2 * v2;
    #pragma unroll
    for (int o = 16; o; o >>= 1) {
        s  += __shfl_xor_sync(0xffffffffu, s, o);
        s2 += __shfl_xor_sync(0xffffffffu, s2, o);
    }
    if (lane == 0) { red[wid] = s; red2[wid] = s2; }
    __syncthreads();
    if (tid == 0) {
        float tt = 0.f, t2 = 0.f;
        #pragma unroll
        for (int i = 0; i < 8; i++) { tt += red[i]; t2 += red2[i]; }
        const float mean = tt / (float)DD;
        const float var = (t2 - (float)DD * mean * mean) / (float)(DD - 1);
        s_mean = mean;
        s_scale = alpha_p[0] / (sqrtf(fmaxf(var, 0.f)) + 1e-6f);
    }
    __syncthreads();
    const float mean = s_mean, scale = s_scale, bias = bias_p[0];

    thi[(size_t)row * DD + tid]       = __float2half((v0 - mean) * scale + bias);
    thi[(size_t)row * DD + tid + 256] = __float2half((v1 - mean) * scale + bias);
    thi[(size_t)row * DD + tid + 512] = __float2half((v2 - mean) * scale + bias);
}

// ---------------------------------------------------------------- HMMA GEMM: 8 warps, warp tile 64x32, 2-stage K64
// All fp16 inputs. ACC: 0 = fp32 accum (FFN), 1 = fp16 accum (attention branch).
struct GemmArgs {
    const __half *A;
    const __half *B0, *B1, *B2;
    float *C0, *C1, *C2;
    const float *bias, *res;
    __half *S0, *S1, *S2;
    int relu, N, K, splitk;
};

#define GP 144
#define GTILE (128 * GP)
#define GSTG  (2 * GTILE)
#define GSMEM (2 * GSTG)

template<int ACC>
__global__ void __launch_bounds__(256, 2) mma_gemm(GemmArgs ga)
{
    extern __shared__ char smc[];
    const uint32_t smb = smem_to_u32(smc);
    const int tid = threadIdx.x, wid = tid >> 5, lane = tid & 31;
    const int bn = blockIdx.x * 128, bm = blockIdx.y * 128;
    const int z = blockIdx.z;
    const int sk = ga.splitk;
    const __half* A = ga.A;
    const __half* B; float* C; __half* Sh;
    int c0, NC;
    if (sk > 1) {
        B = ga.B0; C = ga.C0; Sh = nullptr;
        NC = ga.K / 64 / sk;
        c0 = z * NC;
    } else {
        B = (z == 0) ? ga.B0 : ((z == 1) ? ga.B1 : ga.B2);
        C = (z == 0) ? ga.C0 : ((z == 1) ? ga.C1 : ga.C2);
        Sh = (z == 0) ? ga.S0 : ((z == 1) ? ga.S1 : ga.S2);
        NC = ga.K / 64;
        c0 = 0;
    }
    const int K = ga.K;

    const int wm64 = (wid & 1) * 64;
    const int wn32 = (wid >> 1) * 32;

    float    accf[4][4][4];
    uint32_t acch[4][4][2];
    #pragma unroll
    for (int f = 0; f < 4; f++)
        #pragma unroll
        for (int n = 0; n < 4; n++) {
            if constexpr (ACC == 0) {
                #pragma unroll
                for (int e = 0; e < 4; e++) accf[f][n][e] = 0.f;
            } else {
                acch[f][n][0] = 0u; acch[f][n][1] = 0u;
            }
        }

    auto issue = [&](int c) {
        const int ks = (c0 + c) * 64;
        const uint32_t base = smb + (uint32_t)(c & 1) * GSTG;
        #pragma unroll
        for (int i = 0; i < 8; i++) {
            const int u = tid + i * 256;
            const int row = (u >> 3) & 127, c16 = u & 7;
            const uint32_t dst = base + ((u < 1024) ? 0u : (uint32_t)GTILE)
                               + row * GP + c16 * 16;
            const __half* src = (u < 1024)
                ? (A + (size_t)(bm + row) * K + ks + c16 * 8)
                : (B + (size_t)(bn + row) * K + ks + c16 * 8);
            cp16(dst, src);
        }
        CP_COMMIT();
    };

    issue(0);
    if (NC > 1) issue(1);

    const uint32_t aBase0 = smb + (uint32_t)((wm64 + (lane & 15)) * GP + ((lane >> 4) << 3) * 2);
    const uint32_t bBase0 = smb + (uint32_t)GTILE
                          + (uint32_t)((wn32 + ((lane >> 4) << 3) + (lane & 7)) * GP
                                       + (((lane >> 3) & 1) << 3) * 2);

    for (int c = 0; c < NC; c++) {
        if (c + 1 < NC) { CP_WAIT1(); } else { CP_WAIT0(); }
        __syncthreads();

        const uint32_t stg = (uint32_t)(c & 1) * GSTG;
        uint32_t aAddr = aBase0 + stg;
        uint32_t bAddr = bBase0 + stg;
        #pragma unroll
        for (int kk = 0; kk < 4; kk++) {
            uint32_t af[4][4];
            #pragma unroll
            for (int f = 0; f < 4; f++)
                ldsm_x4(af[f], aAddr + (uint32_t)(f * 16 * GP));
            uint32_t bq[2][4];
            #pragma unroll
            for (int p = 0; p < 2; p++)
                ldsm_x4(bq[p], bAddr + (uint32_t)(p * 16 * GP));
            aAddr += 32;
            bAddr += 32;
            #pragma unroll
            for (int f = 0; f < 4; f++) {
                #pragma unroll
                for (int p = 0; p < 2; p++) {
                    uint32_t b0[2] = { bq[p][0], bq[p][1] };
                    uint32_t b1[2] = { bq[p][2], bq[p][3] };
                    if constexpr (ACC == 0) {
                        mma_f32a(accf[f][2 * p],     af[f], b0);
                        mma_f32a(accf[f][2 * p + 1], af[f], b1);
                    } else {
                        mma_f16a(acch[f][2 * p],     af[f], b0);
                        mma_f16a(acch[f][2 * p + 1], af[f], b1);
                    }
                }
            }
        }
        __syncthreads();
        if (c + 2 < NC) issue(c + 2);
    }

    // ---- epilogue
    const int gq = lane >> 2, t4 = lane & 3;
    #pragma unroll
    for (int f = 0; f < 4; f++) {
        #pragma unroll
        for (int half = 0; half < 2; half++) {
            const int m = bm + wm64 + f * 16 + gq + half * 8;
            const size_t rowo = (size_t)m * ga.N;
            #pragma unroll
            for (int n = 0; n < 4; n++) {
                const int col = bn + wn32 + n * 8 + t4 * 2;
                float vx, vy;
                if constexpr (ACC == 0) {
                    vx = accf[f][n][half * 2 + 0];
                    vy = accf[f][n][half * 2 + 1];
                } else {
                    float2 fv = __half22float2(*(__half2*)&acch[f][n][half]);
                    vx = fv.x; vy = fv.y;
                }
                if (sk > 1) {
                    red_add2(C + rowo + col, vx, vy);   // C pre-seeded with res(+bias)
                    continue;
                }
                if (ga.bias) {
                    float2 bb = *(const float2*)(ga.bias + col);
                    vx += bb.x; vy += bb.y;
                }
                if (ga.relu) { vx = fmaxf(vx, 0.f); vy = fmaxf(vy, 0.f); }
                if (ga.res) {
                    float2 rr = *(const float2*)(ga.res + rowo + col);
                    vx += rr.x; vy += rr.y;
                }
                if (Sh) {
                    *(uint32_t*)(Sh + rowo + col) = pack_h2(vx, vy);
                } else {
                    *(float2*)(C + rowo + col) = make_float2(vx, vy);
                }
            }
        }
    }
}

// ---------------------------------------------------------------- HMMA flash attention (fp16, fp16 accum)
#define FPITCH 144
#define FQOFF 0
#define FQSZ  (128 * FPITCH)
#define FKOFF FQSZ
#define FSTG  (2 * 64 * FPITCH)
#define FMOFF (FKOFF + 2 * FSTG)
#define FSMEM (FMOFF + 512)

__global__ void __launch_bounds__(256, 2) flash_mma(
    const __half* __restrict__ Qb, const __half* __restrict__ Kb,
    const __half* __restrict__ Vb, const int* __restrict__ mask,
    __half* __restrict__ Ohi)
{
    extern __shared__ char fsm[];
    const uint32_t smb = smem_to_u32(fsm);
    const int tid = threadIdx.x, wid = tid >> 5, lane = tid & 31;
    const int gq = lane >> 2, t4 = lane & 3;
    const int bh = blockIdx.x, b = bh / HH, h = bh % HH;
    const int q0 = blockIdx.y * 128;
    const int NIT = SS / 64;

    auto cpKV = [&](int it, int st) {
        const uint32_t ks = smb + FKOFF + st * FSTG;
        const uint32_t vs = ks + 64 * FPITCH;
        const __half* Ksrc = Kb + (size_t)(b * SS + it * 64) * DD + h * 64;
        const __half* Vsrc = Vb + (size_t)(b * SS + it * 64) * DD + h * 64;
        #pragma unroll
        for (int i = 0; i < 2; i++) {
            const int idx = tid + i * 256;
            const int r = idx >> 3, c = idx & 7;
            cp16(ks + r * FPITCH + c * 16, Ksrc + (size_t)r * DD + c * 8);
            cp16(vs + r * FPITCH + c * 16, Vsrc + (size_t)r * DD + c * 8);
        }
        if (tid < 16)
            cp16(smb + FMOFF + st * 256 + tid * 16, mask + b * SS + it * 64 + tid * 4);
        CP_COMMIT();
    };

    {
        const __half* Qsrc = Qb + (size_t)(b * SS + q0) * DD + h * 64;
        #pragma unroll
        for (int i = 0; i < 4; i++) {
            const int idx = tid + i * 256;
            const int r = idx >> 3, c = idx & 7;
            cp16(smb + FQOFF + r * FPITCH + c * 16, Qsrc + (size_t)r * DD + c * 8);
        }
        const uint32_t ks = smb + FKOFF;
        const uint32_t vs = ks + 64 * FPITCH;
        const __half* Ksrc = Kb + (size_t)(b * SS) * DD + h * 64;
        const __half* Vsrc = Vb + (size_t)(b * SS) * DD + h * 64;
        #pragma unroll
        for (int i = 0; i < 2; i++) {
            const int idx = tid + i * 256;
            const int r = idx >> 3, c = idx & 7;
            cp16(ks + r * FPITCH + c * 16, Ksrc + (size_t)r * DD + c * 8);
            cp16(vs + r * FPITCH + c * 16, Vsrc + (size_t)r * DD + c * 8);
        }
        if (tid < 16)
            cp16(smb + FMOFF + tid * 16, mask + b * SS + tid * 4);
        CP_COMMIT();
        cpKV(1, 1);
    }

    CP_WAIT1();
    __syncthreads();

    uint32_t aq[4][4];
    #pragma unroll
    for (int kc = 0; kc < 4; kc++) {
        uint32_t addr = smb + FQOFF
                      + (uint32_t)((wid * 16 + (lane & 15)) * FPITCH
                                   + (kc * 16 + ((lane >> 4) << 3)) * 2);
        ldsm_x4(aq[kc], addr);
    }

    uint32_t oacc[8][2];
    #pragma unroll
    for (int n = 0; n < 8; n++) { oacc[n][0] = 0u; oacc[n][1] = 0u; }
    float l0 = 0.f, l1 = 0.f;

    for (int it = 0; it < NIT; it++) {
        if (it > 0) {
            if (it + 1 < NIT) { CP_WAIT1(); } else { CP_WAIT0(); }
            __syncthreads();
        }
        const int st = it & 1;
        const uint32_t ks = smb + FKOFF + st * FSTG;
        const uint32_t vs = ks + 64 * FPITCH;
        const int* Mi = (const int*)(fsm + FMOFF + st * 256);

        uint32_t s16[8][2];
        #pragma unroll
        for (int j = 0; j < 8; j++) { s16[j][0] = 0u; s16[j][1] = 0u; }

        #pragma unroll
        for (int kc = 0; kc < 4; kc++) {
            uint32_t bfr[4][4];
            #pragma unroll
            for (int jj = 0; jj < 4; jj++) {
                uint32_t addr = ks + (uint32_t)((jj * 16 + ((lane >> 4) << 3) + (lane & 7)) * FPITCH
                                                + (kc * 16 + (((lane >> 3) & 1) << 3)) * 2);
                ldsm_x4(bfr[jj], addr);
            }
            #pragma unroll
            for (int jj = 0; jj < 4; jj++) {
                uint32_t b0[2] = { bfr[jj][0], bfr[jj][1] };
                uint32_t b1[2] = { bfr[jj][2], bfr[jj][3] };
                mma_f16a(s16[2 * jj],     aq[kc], b0);
                mma_f16a(s16[2 * jj + 1], aq[kc], b1);
            }
        }

        uint32_t pf[8][2];
        #pragma unroll
        for (int j = 0; j < 8; j++) {
            const int col = j * 8 + t4 * 2;
            const int m0 = Mi[col], m1 = Mi[col + 1];
            float2 sa = __half22float2(*(__half2*)&s16[j][0]);   // row gq
            float2 sb = __half22float2(*(__half2*)&s16[j][1]);   // row gq+8
            float v0 = m0 ? sa.x * 0.125f : 1e-9f;
            float v1 = m1 ? sa.y * 0.125f : 1e-9f;
            float v2 = m0 ? sb.x * 0.125f : 1e-9f;
            float v3 = m1 ? sb.y * 0.125f : 1e-9f;
            float p0 = __expf(v0), p1 = __expf(v1), p2 = __expf(v2), p3 = __expf(v3);
            l0 += p0 + p1;
            l1 += p2 + p3;
            pf[j][0] = pack_h2(p0, p1);
            pf[j][1] = pack_h2(p2, p3);
        }

        #pragma unroll
        for (int jk = 0; jk < 4; jk++) {
            uint32_t a[4] = { pf[2 * jk][0], pf[2 * jk][1], pf[2 * jk + 1][0], pf[2 * jk + 1][1] };
            #pragma unroll
            for (int nn = 0; nn < 4; nn++) {
                uint32_t bv[4];
                uint32_t addr = vs + (uint32_t)((jk * 16 + (((lane >> 3) & 1) << 3) + (lane & 7)) * FPITCH
                                                + (nn * 16 + ((lane >> 4) << 3)) * 2);
                ldsm_x4_t(bv, addr);
                uint32_t b0[2] = { bv[0], bv[1] };
                uint32_t b1[2] = { bv[2], bv[3] };
                mma_f16a(oacc[2 * nn],     a, b0);
                mma_f16a(oacc[2 * nn + 1], a, b1);
            }
        }

        __syncthreads();
        if (it + 2 < NIT) cpKV(it + 2, st);
    }

    l0 += __shfl_xor_sync(0xffffffffu, l0, 1);
    l0 += __shfl_xor_sync(0xffffffffu, l0, 2);
    l1 += __shfl_xor_sync(0xffffffffu, l1, 1);
    l1 += __shfl_xor_sync(0xffffffffu, l1, 2);
    const float inv0 = 1.f / l0, inv1 = 1.f / l1;

    const int r0 = b * SS + q0 + wid * 16 + gq;
    const int r1 = r0 + 8;
    #pragma unroll
    for (int nn = 0; nn < 8; nn++) {
        const int col = h * 64 + nn * 8 + t4 * 2;
        float2 o0 = __half22float2(*(__half2*)&oacc[nn][0]);
        float2 o1 = __half22float2(*(__half2*)&oacc[nn][1]);
        *(uint32_t*)(Ohi + (size_t)r0 * DD + col) = pack_h2(o0.x * inv0, o0.y * inv0);
        *(uint32_t*)(Ohi + (size_t)r1 * DD + col) = pack_h2(o1.x * inv1, o1.y * inv1);
    }
}

// ---------------------------------------------------------------- launch
extern "C" void kernel_launch(void* const* d_in, const int* in_sizes, int n_in,
                              void* d_out, int out_size)
{
    const float* x    = (const float*)d_in[0];
    const int*   mask = (const int*)  d_in[1];
    const float* wq   = (const float*)d_in[2];
    const float* wk   = (const float*)d_in[3];
    const float* wv   = (const float*)d_in[4];
    const float* wo   = (const float*)d_in[5];
    const float* w1   = (const float*)d_in[6];
    const float* b1   = (const float*)d_in[7];
    const float* w2   = (const float*)d_in[8];
    const float* b2   = (const float*)d_in[9];
    const float* ln1a = (const float*)d_in[10];
    const float* ln1b = (const float*)d_in[11];
    const float* ln2a = (const float*)d_in[12];
    const float* ln2b = (const float*)d_in[13];
    float* out = (float*)d_out;

    __half *t16, *h1, *qb, *kb, *vb, *chi;
    __half *wqh, *wkh, *wvh, *woh, *w1h, *w2h;
    float *x2;
    cudaGetSymbolAddress((void**)&t16, g_t16);
    cudaGetSymbolAddress((void**)&chi, g_chi);
    cudaGetSymbolAddress((void**)&h1, g_h1);
    cudaGetSymbolAddress((void**)&qb, g_qb);   cudaGetSymbolAddress((void**)&kb, g_kb);
    cudaGetSymbolAddress((void**)&vb, g_vb);
    cudaGetSymbolAddress((void**)&wqh, g_wqh);
    cudaGetSymbolAddress((void**)&wkh, g_wkh);
    cudaGetSymbolAddress((void**)&wvh, g_wvh);
    cudaGetSymbolAddress((void**)&woh, g_woh);
    cudaGetSymbolAddress((void**)&w1h, g_w1h);
    cudaGetSymbolAddress((void**)&w2h, g_w2h);
    cudaGetSymbolAddress((void**)&x2, g_x2);

    cudaFuncSetAttribute(mma_gemm<0>, cudaFuncAttributeMaxDynamicSharedMemorySize, GSMEM);
    cudaFuncSetAttribute(mma_gemm<1>, cudaFuncAttributeMaxDynamicSharedMemorySize, GSMEM);
    cudaFuncSetAttribute(flash_mma, cudaFuncAttributeMaxDynamicSharedMemorySize, FSMEM);

    // merged prologue: weight transpose (all fp16) + LN1 (+x2 = x seed)
    WSArgs wa = {};
    wa.W[0] = wq; wa.Hi[0] = wqh; wa.Kd[0] = DD; wa.Nd[0] = DD;
    wa.W[1] = wk; wa.Hi[1] = wkh; wa.Kd[1] = DD; wa.Nd[1] = DD;
    wa.W[2] = wv; wa.Hi[2] = wvh; wa.Kd[2] = DD; wa.Nd[2] = DD;
    wa.W[3] = wo; wa.Hi[3] = woh; wa.Kd[3] = DD; wa.Nd[3] = DD;
    wa.W[4] = w1; wa.Hi[4] = w1h; wa.Kd[4] = DD; wa.Nd[4] = FF;
    wa.W[5] = w2; wa.Hi[5] = w2h; wa.Kd[5] = FF; wa.Nd[5] = DD;
    int acc0 = 0;
    wa.start[0] = 0;
    for (int e = 0; e < 6; e++) {
        acc0 += (wa.Nd[e] / 64) * (wa.Kd[e] / 64);
        wa.start[e + 1] = acc0;
    }
    prolog_kernel<<<acc0 + NROW, 256>>>(wa, x, t16, ln1a, ln1b, x2);

    // Q/K/V projections (fp16, fp16-accum, z-batched)
    GemmArgs aq = {};
    aq.A = t16;
    aq.B0 = wqh; aq.B1 = wkh; aq.B2 = wvh;
    aq.S0 = qb; aq.S1 = kb; aq.S2 = vb;
    aq.N = DD; aq.K = DD; aq.splitk = 1;
    mma_gemm<1><<<dim3(DD / 128, NROW / 128, 3), 256, GSMEM>>>(aq);

    // attention -> fp16 context (fp16 accum)
    flash_mma<<<dim3(BB * HH, SS / 128), 256, FSMEM>>>(qb, kb, vb, mask, chi);

    // x2 += ctx @ wo (fp16-accum, split-K=3, vector red; x2 pre-seeded with x)
    GemmArgs ao = {};
    ao.A = chi;
    ao.B0 = woh;
    ao.C0 = x2;
    ao.N = DD; ao.K = DD; ao.splitk = 3;
    mma_gemm<1><<<dim3(DD / 128, NROW / 128, 3), 256, GSMEM>>>(ao);

    // LN2 -> fp16 (seeds out = x2 + b2 for the FFN2 split-K reds)
    ln_kernel<<<NROW, 256>>>(x2, t16, ln2a, ln2b, out, b2);

    // FFN1: h1 = relu(t @ w1 + b1) (fp16 in, fp32 accum)
    GemmArgs a1 = {};
    a1.A = t16;
    a1.B0 = w1h;
    a1.bias = b1; a1.relu = 1;
    a1.S0 = h1;
    a1.N = FF; a1.K = DD; a1.splitk = 1;
    mma_gemm<0><<<dim3(FF / 128, NROW / 128, 1), 256, GSMEM>>>(a1);

    // FFN2: out += h1 @ w2 (fp16 in, fp32 accum, split-K=3, vector red)
    GemmArgs a2 = {};
    a2.A = h1;
    a2.B0 = w2h;
    a2.C0 = out;
    a2.N = DD; a2.K = FF; a2.splitk = 3;
    mma_gemm<0><<<dim3(DD / 128, NROW / 128, 3), 256, GSMEM>>>(a2);
}